// round 12
// baseline (speedup 1.0000x reference)
#include <cuda_runtime.h>
#include <cuda_fp16.h>
#include <cstdint>
#include <math.h>

#define NPTS 8192
#define PD   16
#define IND  256
#define OUTD 128
#define HH0  512
#define HH1  1024
#define HH2  1024
#define HH3  512
#define NP   (NPTS*PD)   // 131072

// ---------------------------------------------------------------------------
// Device-global scratch (allocation-free per harness rules)
// ---------------------------------------------------------------------------
__device__ __half g_xh[(size_t)NP * IND];
__device__ __half g_xl[(size_t)NP * IND];
__device__ __half g_h0h[(size_t)NP * HH0];
__device__ __half g_h0l[(size_t)NP * HH0];
__device__ __half g_h1h[(size_t)NP * HH1];
__device__ __half g_h1l[(size_t)NP * HH1];
__device__ __half g_h2h[(size_t)NP * HH2];
__device__ __half g_h2l[(size_t)NP * HH2];
__device__ __half g_h3h[(size_t)NP * HH3];
__device__ __half g_h3l[(size_t)NP * HH3];
__device__ __half g_wih[(size_t)PD * HH0 * IND];
__device__ __half g_wil[(size_t)PD * HH0 * IND];
__device__ __half g_w1h[(size_t)HH1 * HH0];
__device__ __half g_w1l[(size_t)HH1 * HH0];
__device__ __half g_w2h[(size_t)HH2 * HH1];
__device__ __half g_w2l[(size_t)HH2 * HH1];
__device__ __half g_w3h[(size_t)HH3 * HH2];
__device__ __half g_w3l[(size_t)HH3 * HH2];
__device__ __half g_woh[(size_t)PD * 2 * OUTD * HH3];
__device__ __half g_wol[(size_t)PD * 2 * OUTD * HH3];

// ---------------------------------------------------------------------------
// Helpers
// ---------------------------------------------------------------------------
__device__ __forceinline__ uint32_t smem_u32(const void* p) {
    uint32_t a;
    asm("{ .reg .u64 t; cvta.to.shared.u64 t, %1; cvt.u32.u64 %0, t; }" : "=r"(a) : "l"(p));
    return a;
}
__device__ __forceinline__ void cp16(uint32_t dst, const void* src) {
    asm volatile("cp.async.cg.shared.global [%0], [%1], 16;" :: "r"(dst), "l"(src));
}
__device__ __forceinline__ void cp_commit() {
    asm volatile("cp.async.commit_group;" ::: "memory");
}
__device__ __forceinline__ void cp_wait0() {
    asm volatile("cp.async.wait_group 0;" ::: "memory");
}
__device__ __forceinline__ void ldsm4(uint32_t* r, uint32_t addr) {
    asm volatile("ldmatrix.sync.aligned.m8n8.x4.shared.b16 {%0,%1,%2,%3}, [%4];"
                 : "=r"(r[0]), "=r"(r[1]), "=r"(r[2]), "=r"(r[3]) : "r"(addr));
}
__device__ __forceinline__ void mma16816(float* d, const uint32_t* a, const uint32_t* b) {
    asm volatile("mma.sync.aligned.m16n8k16.row.col.f32.f16.f16.f32 "
                 "{%0,%1,%2,%3}, {%4,%5,%6,%7}, {%8,%9}, {%0,%1,%2,%3};"
                 : "+f"(d[0]), "+f"(d[1]), "+f"(d[2]), "+f"(d[3])
                 : "r"(a[0]), "r"(a[1]), "r"(a[2]), "r"(a[3]), "r"(b[0]), "r"(b[1]));
}
__device__ __forceinline__ float softplusf(float x) {
    return fmaxf(x, 0.0f) + log1pf(expf(-fabsf(x)));
}

// ---------------------------------------------------------------------------
// fp32 -> (hi, lo) fp16 split converter: ONE launch for all 6 tensors.
// ---------------------------------------------------------------------------
__device__ __forceinline__ void cvt_body(const float* __restrict__ s,
                                         __half* __restrict__ hi, __half* __restrict__ lo,
                                         long n4, long i, long stride)
{
    for (; i < n4; i += stride) {
        float4 v = ((const float4*)s)[i];
        __half h0 = __float2half_rn(v.x), h1 = __float2half_rn(v.y);
        __half h2 = __float2half_rn(v.z), h3 = __float2half_rn(v.w);
        __half l0 = __float2half_rn(v.x - __half2float(h0));
        __half l1 = __float2half_rn(v.y - __half2float(h1));
        __half l2 = __float2half_rn(v.z - __half2float(h2));
        __half l3 = __float2half_rn(v.w - __half2float(h3));
        ((__half2*)hi)[2 * i]     = __halves2half2(h0, h1);
        ((__half2*)hi)[2 * i + 1] = __halves2half2(h2, h3);
        ((__half2*)lo)[2 * i]     = __halves2half2(l0, l1);
        ((__half2*)lo)[2 * i + 1] = __halves2half2(l2, l3);
    }
}

__global__ void cvt_all(const float* s0, __half* h0, __half* l0, long n0,
                        const float* s1, __half* h1, __half* l1, long n1,
                        const float* s2, __half* h2, __half* l2, long n2,
                        const float* s3, __half* h3, __half* l3, long n3,
                        const float* s4, __half* h4, __half* l4, long n4_,
                        const float* s5, __half* h5, __half* l5, long n5)
{
    const long i = blockIdx.x * (long)blockDim.x + threadIdx.x;
    const long st = (long)gridDim.x * blockDim.x;
    switch (blockIdx.y) {
        case 0: cvt_body(s0, h0, l0, n0, i, st); break;   // x (largest)
        case 1: cvt_body(s1, h1, l1, n1, i, st); break;
        case 2: cvt_body(s2, h2, l2, n2, i, st); break;
        case 3: cvt_body(s3, h3, l3, n3, i, st); break;
        case 4: cvt_body(s4, h4, l4, n4_, i, st); break;
        case 5: cvt_body(s5, h5, l5, n5, i, st); break;
    }
}

// ---------------------------------------------------------------------------
// fp16x2-split tensor-core GEMM: C[m,n] = sum_k A[m,k]*W[n,k] + bias[n]
// CTA tile 64(M)x128(N), 128 threads = 4 warps (2M x 2N), warp tile 32x64.
// GRID: blockIdx.x = n-tile (FAST) so the CTAs sharing one A tile are
// co-resident in a wave -> A streams from DRAM once, re-hits in L2.
// blockIdx.y = m-tile, blockIdx.z = p.
// K-chunk 32, 2-stage cp.async pipeline, ONE __syncthreads per chunk.
// TERM-MAJOR MMA ordering (reuse distance 16 covers HMMA RAW latency).
// 3 CTAs/SM (12 warps), <=170 regs. 80B-padded rows -> ldmatrix conflict-free.
// EPI: 0 linear (hi/lo out), 1 relu (hi/lo out), 2 final head (fp32 out,
//      n-tile 0 = mu, 1 = var(softplus), mask -> NaN)
// ---------------------------------------------------------------------------
#define ROWB  80
#define TA_H  0
#define TA_L  5120
#define TB_H  10240
#define TB_L  20480
#define STG   30720
#define SBIAS (2*STG)
#define SMEMT (2*STG + 512)

template<int EPI>
__global__ void __launch_bounds__(128, 3)
hgemm(const __half* __restrict__ Ah, const __half* __restrict__ Al, long lda, long Az,
      const __half* __restrict__ Wh, const __half* __restrict__ Wl, long Wz,
      const float* __restrict__ Bv, long Bz,
      __half* __restrict__ Ch, __half* __restrict__ Cl, long ldc, long Cz,
      float* __restrict__ Fout, const unsigned char* __restrict__ mask,
      int K)
{
    extern __shared__ char smem[];
    const uint32_t sb = smem_u32(smem);
    const int tid = threadIdx.x;
    const int wid = tid >> 5;
    const int l   = tid & 31;
    const long n0 = (long)blockIdx.x * 128;   // n FAST -> A tile L2 reuse
    const long m0 = (long)blockIdx.y * 64;
    const int  z  = blockIdx.z;

    Ah += (long)z * Az + m0 * lda;
    Al += (long)z * Az + m0 * lda;
    Wh += (long)z * Wz + n0 * (long)K;
    Wl += (long)z * Wz + n0 * (long)K;
    Bv += (long)z * Bz + n0;

    ((float*)(smem + SBIAS))[tid] = Bv[tid];   // 128 threads, 128 floats

    // Load slots (K-chunk 32 = 64B/row = 4 x 16B):
    //   A arrays: 64 rows x 4 chunks = 256 ops -> 2/thread per array
    //   B arrays: 128 rows x 4 chunks = 512 ops -> 4/thread per array
    const int ar0 = tid >> 2,           ac0 = tid & 3;
    const int ar1 = (tid + 128) >> 2,   ac1 = (tid + 128) & 3;
    const int br2 = (tid + 256) >> 2,   bc2 = (tid + 256) & 3;
    const int br3 = (tid + 384) >> 2,   bc3 = (tid + 384) & 3;

    const int NC = K >> 5;

    auto issue = [&](int stage) {
        const int k0 = stage << 5;
        const uint32_t st = sb + (uint32_t)(stage & 1) * STG;
        cp16(st + TA_H + ar0 * ROWB + ac0 * 16, Ah + (long)ar0 * lda + k0 + ac0 * 8);
        cp16(st + TA_H + ar1 * ROWB + ac1 * 16, Ah + (long)ar1 * lda + k0 + ac1 * 8);
        cp16(st + TA_L + ar0 * ROWB + ac0 * 16, Al + (long)ar0 * lda + k0 + ac0 * 8);
        cp16(st + TA_L + ar1 * ROWB + ac1 * 16, Al + (long)ar1 * lda + k0 + ac1 * 8);
        cp16(st + TB_H + ar0 * ROWB + ac0 * 16, Wh + (long)ar0 * K + k0 + ac0 * 8);
        cp16(st + TB_H + ar1 * ROWB + ac1 * 16, Wh + (long)ar1 * K + k0 + ac1 * 8);
        cp16(st + TB_H + br2 * ROWB + bc2 * 16, Wh + (long)br2 * K + k0 + bc2 * 8);
        cp16(st + TB_H + br3 * ROWB + bc3 * 16, Wh + (long)br3 * K + k0 + bc3 * 8);
        cp16(st + TB_L + ar0 * ROWB + ac0 * 16, Wl + (long)ar0 * K + k0 + ac0 * 8);
        cp16(st + TB_L + ar1 * ROWB + ac1 * 16, Wl + (long)ar1 * K + k0 + ac1 * 8);
        cp16(st + TB_L + br2 * ROWB + bc2 * 16, Wl + (long)br2 * K + k0 + bc2 * 8);
        cp16(st + TB_L + br3 * ROWB + bc3 * 16, Wl + (long)br3 * K + k0 + bc3 * 8);
    };

    issue(0); cp_commit();

    const int warp_m = wid & 1;        // 0..1 -> m offset *32
    const int warp_n = wid >> 1;       // 0..1 -> n offset *64
    const int a_r = l & 15;
    const int a_k = (l >> 4) * 8;
    const int b_r = (l & 7) + ((l >> 4) << 3);
    const int b_k = ((l >> 3) & 1) * 8;

    float acc[2][8][4] = {};

    for (int i = 0; i < NC; i++) {
        cp_wait0();            // stage i arrived (only group in flight)
        __syncthreads();       // + all warps finished stage i-1's buffer
        if (i + 1 < NC) { issue(i + 1); cp_commit(); }

        const uint32_t st = sb + (uint32_t)(i & 1) * STG;
        #pragma unroll
        for (int ks = 0; ks < 32; ks += 16) {
            // ---- load ALL fragments for this half-chunk ----
            uint32_t ahf[2][4], alf[2][4];
            #pragma unroll
            for (int mt = 0; mt < 2; mt++) {
                const uint32_t arow = (warp_m * 32 + mt * 16 + a_r) * ROWB + (ks + a_k) * 2;
                ldsm4(ahf[mt], st + TA_H + arow);
                ldsm4(alf[mt], st + TA_L + arow);
            }
            uint32_t bhf[4][4], blf[4][4];
            #pragma unroll
            for (int g = 0; g < 4; g++) {
                const uint32_t brow = (warp_n * 64 + g * 16 + b_r) * ROWB + (ks + b_k) * 2;
                ldsm4(bhf[g], st + TB_H + brow);
                ldsm4(blf[g], st + TB_L + brow);
            }
            // ---- term-major MMA issue: 16 independent per term ----
            #pragma unroll
            for (int g = 0; g < 4; g++)        // hi*hi
                #pragma unroll
                for (int mt = 0; mt < 2; mt++)
                    #pragma unroll
                    for (int pr = 0; pr < 2; pr++)
                        mma16816(acc[mt][g * 2 + pr], ahf[mt], &bhf[g][pr * 2]);
            #pragma unroll
            for (int g = 0; g < 4; g++)        // hi*lo
                #pragma unroll
                for (int mt = 0; mt < 2; mt++)
                    #pragma unroll
                    for (int pr = 0; pr < 2; pr++)
                        mma16816(acc[mt][g * 2 + pr], ahf[mt], &blf[g][pr * 2]);
            #pragma unroll
            for (int g = 0; g < 4; g++)        // lo*hi
                #pragma unroll
                for (int mt = 0; mt < 2; mt++)
                    #pragma unroll
                    for (int pr = 0; pr < 2; pr++)
                        mma16816(acc[mt][g * 2 + pr], alf[mt], &bhf[g][pr * 2]);
        }
    }

    // ---- epilogue ----
    const float* bias_s = (const float*)(smem + SBIAS);

    #pragma unroll
    for (int mt = 0; mt < 2; mt++) {
        const long gr0 = m0 + warp_m * 32 + mt * 16 + (l >> 2);
        const long gr1 = gr0 + 8;
        #pragma unroll
        for (int nf = 0; nf < 8; nf++) {
            const int c = warp_n * 64 + nf * 8 + (l & 3) * 2;
            const float b0 = bias_s[c], b1 = bias_s[c + 1];
            float v00 = acc[mt][nf][0] + b0, v01 = acc[mt][nf][1] + b1;
            float v10 = acc[mt][nf][2] + b0, v11 = acc[mt][nf][3] + b1;

            if (EPI == 1) {
                v00 = fmaxf(v00, 0.f); v01 = fmaxf(v01, 0.f);
                v10 = fmaxf(v10, 0.f); v11 = fmaxf(v11, 0.f);
            }

            if (EPI != 2) {
                __half h00 = __float2half_rn(v00), h01 = __float2half_rn(v01);
                __half h10 = __float2half_rn(v10), h11 = __float2half_rn(v11);
                __half l00 = __float2half_rn(v00 - __half2float(h00));
                __half l01 = __float2half_rn(v01 - __half2float(h01));
                __half l10 = __float2half_rn(v10 - __half2float(h10));
                __half l11 = __float2half_rn(v11 - __half2float(h11));
                __half* ch0 = Ch + (long)z * Cz + gr0 * ldc + n0 + c;
                __half* ch1 = Ch + (long)z * Cz + gr1 * ldc + n0 + c;
                __half* cl0 = Cl + (long)z * Cz + gr0 * ldc + n0 + c;
                __half* cl1 = Cl + (long)z * Cz + gr1 * ldc + n0 + c;
                *(__half2*)ch0 = __halves2half2(h00, h01);
                *(__half2*)ch1 = __halves2half2(h10, h11);
                *(__half2*)cl0 = __halves2half2(l00, l01);
                *(__half2*)cl1 = __halves2half2(l10, l11);
            } else {
                const int y = blockIdx.x;           // n-tile: 0 = mu, 1 = var
                if (y == 1) {
                    v00 = 0.01f + 0.99f * softplusf(v00);
                    v01 = 0.01f + 0.99f * softplusf(v01);
                    v10 = 0.01f + 0.99f * softplusf(v10);
                    v11 = 0.01f + 0.99f * softplusf(v11);
                }
                const long f0 = gr0 * PD + z;
                const long f1 = gr1 * PD + z;
                const float nanv = __int_as_float(0x7FC00000);
                float2 o0v = make_float2(v00, v01);
                float2 o1v = make_float2(v10, v11);
                if (mask[f0] != 0) { o0v.x = nanv; o0v.y = nanv; }
                if (mask[f1] != 0) { o1v.x = nanv; o1v.y = nanv; }
                float* ob = Fout + (long)y * ((long)NP * OUTD);
                *(float2*)(ob + f0 * OUTD + c) = o0v;
                *(float2*)(ob + f1 * OUTD + c) = o1v;
            }
        }
    }
}

extern "C" void kernel_launch(void* const* d_in, const int* in_sizes, int n_in,
                              void* d_out, int out_size)
{
    const float* x    = (const float*)d_in[0];
    const unsigned char* mask = (const unsigned char*)d_in[1];
    const float* W_in = (const float*)d_in[2];
    const float* b_in = (const float*)d_in[3];
    const float* W1   = (const float*)d_in[4];
    const float* b1   = (const float*)d_in[5];
    const float* W2   = (const float*)d_in[6];
    const float* b2   = (const float*)d_in[7];
    const float* W3   = (const float*)d_in[8];
    const float* b3   = (const float*)d_in[9];
    const float* Wout = (const float*)d_in[10];
    const float* bout = (const float*)d_in[11];
    float* out = (float*)d_out;

    __half *xh, *xl, *h0h, *h0l, *h1h, *h1l, *h2h, *h2l, *h3h, *h3l;
    __half *wih, *wil, *w1h, *w1l, *w2h, *w2l, *w3h, *w3l, *woh, *wol;
    cudaGetSymbolAddress((void**)&xh,  g_xh);  cudaGetSymbolAddress((void**)&xl,  g_xl);
    cudaGetSymbolAddress((void**)&h0h, g_h0h); cudaGetSymbolAddress((void**)&h0l, g_h0l);
    cudaGetSymbolAddress((void**)&h1h, g_h1h); cudaGetSymbolAddress((void**)&h1l, g_h1l);
    cudaGetSymbolAddress((void**)&h2h, g_h2h); cudaGetSymbolAddress((void**)&h2l, g_h2l);
    cudaGetSymbolAddress((void**)&h3h, g_h3h); cudaGetSymbolAddress((void**)&h3l, g_h3l);
    cudaGetSymbolAddress((void**)&wih, g_wih); cudaGetSymbolAddress((void**)&wil, g_wil);
    cudaGetSymbolAddress((void**)&w1h, g_w1h); cudaGetSymbolAddress((void**)&w1l, g_w1l);
    cudaGetSymbolAddress((void**)&w2h, g_w2h); cudaGetSymbolAddress((void**)&w2l, g_w2l);
    cudaGetSymbolAddress((void**)&w3h, g_w3h); cudaGetSymbolAddress((void**)&w3l, g_w3l);
    cudaGetSymbolAddress((void**)&woh, g_woh); cudaGetSymbolAddress((void**)&wol, g_wol);

    cudaFuncSetAttribute(hgemm<0>, cudaFuncAttributeMaxDynamicSharedMemorySize, SMEMT);
    cudaFuncSetAttribute(hgemm<1>, cudaFuncAttributeMaxDynamicSharedMemorySize, SMEMT);
    cudaFuncSetAttribute(hgemm<2>, cudaFuncAttributeMaxDynamicSharedMemorySize, SMEMT);

    // ---- all conversions: ONE launch ----
    cvt_all<<<dim3(512, 6), 256>>>(
        x,    xh,  xl,  (long)NP * IND / 4,
        W_in, wih, wil, (long)PD * HH0 * IND / 4,
        W1,   w1h, w1l, (long)HH1 * HH0 / 4,
        W2,   w2h, w2l, (long)HH2 * HH1 / 4,
        W3,   w3h, w3l, (long)HH3 * HH2 / 4,
        Wout, woh, wol, (long)PD * 2 * OUTD * HH3 / 4);

    // ---- Layer 0: per-p input projection (linear), n fast ----
    hgemm<0><<<dim3(HH0 / 128, NPTS / 64, PD), 128, SMEMT>>>(
        xh, xl, (long)PD * IND, (long)IND,
        wih, wil, (long)HH0 * IND,
        b_in, (long)HH0,
        h0h, h0l, (long)PD * HH0, (long)HH0,
        nullptr, nullptr, IND);

    // ---- Layer 1: relu, n fast ----
    hgemm<1><<<dim3(HH1 / 128, NP / 64, 1), 128, SMEMT>>>(
        h0h, h0l, HH0, 0, w1h, w1l, 0, b1, 0,
        h1h, h1l, HH1, 0, nullptr, nullptr, HH0);

    // ---- Layer 2: relu, n fast ----
    hgemm<1><<<dim3(HH2 / 128, NP / 64, 1), 128, SMEMT>>>(
        h1h, h1l, HH1, 0, w2h, w2l, 0, b2, 0,
        h2h, h2l, HH2, 0, nullptr, nullptr, HH1);

    // ---- Layer 3: relu, n fast ----
    hgemm<1><<<dim3(HH3 / 128, NP / 64, 1), 128, SMEMT>>>(
        h2h, h2l, HH2, 0, w3h, w3l, 0, b3, 0,
        h3h, h3l, HH3, 0, nullptr, nullptr, HH2);

    // ---- Output head: n fast (x = 0 mu, 1 var(softplus)), mask -> NaN ----
    hgemm<2><<<dim3(2, NPTS / 64, PD), 128, SMEMT>>>(
        h3h, h3l, (long)PD * HH3, (long)HH3,
        woh, wol, (long)(2 * OUTD) * HH3,
        bout, (long)(2 * OUTD),
        nullptr, nullptr, 0, 0,
        out, mask, HH3);
}

// round 13
// speedup vs baseline: 1.0126x; 1.0126x over previous
#include <cuda_runtime.h>
#include <cuda_fp16.h>
#include <cstdint>
#include <math.h>

#define NPTS 8192
#define PD   16
#define IND  256
#define OUTD 128
#define HH0  512
#define HH1  1024
#define HH2  1024
#define HH3  512
#define NP   (NPTS*PD)   // 131072

// ---------------------------------------------------------------------------
// Device-global scratch (allocation-free per harness rules)
// ---------------------------------------------------------------------------
__device__ __half g_xh[(size_t)NP * IND];
__device__ __half g_xl[(size_t)NP * IND];
__device__ __half g_h0h[(size_t)NP * HH0];
__device__ __half g_h0l[(size_t)NP * HH0];
__device__ __half g_h1h[(size_t)NP * HH1];
__device__ __half g_h1l[(size_t)NP * HH1];
__device__ __half g_h2h[(size_t)NP * HH2];
__device__ __half g_h2l[(size_t)NP * HH2];
__device__ __half g_h3h[(size_t)NP * HH3];
__device__ __half g_h3l[(size_t)NP * HH3];
__device__ __half g_wih[(size_t)PD * HH0 * IND];
__device__ __half g_wil[(size_t)PD * HH0 * IND];
__device__ __half g_w1h[(size_t)HH1 * HH0];
__device__ __half g_w1l[(size_t)HH1 * HH0];
__device__ __half g_w2h[(size_t)HH2 * HH1];
__device__ __half g_w2l[(size_t)HH2 * HH1];
__device__ __half g_w3h[(size_t)HH3 * HH2];
__device__ __half g_w3l[(size_t)HH3 * HH2];
__device__ __half g_woh[(size_t)PD * 2 * OUTD * HH3];
__device__ __half g_wol[(size_t)PD * 2 * OUTD * HH3];

// ---------------------------------------------------------------------------
// Helpers
// ---------------------------------------------------------------------------
__device__ __forceinline__ uint32_t smem_u32(const void* p) {
    uint32_t a;
    asm("{ .reg .u64 t; cvta.to.shared.u64 t, %1; cvt.u32.u64 %0, t; }" : "=r"(a) : "l"(p));
    return a;
}
__device__ __forceinline__ void cp16(uint32_t dst, const void* src) {
    asm volatile("cp.async.cg.shared.global [%0], [%1], 16;" :: "r"(dst), "l"(src));
}
__device__ __forceinline__ void cp_commit() {
    asm volatile("cp.async.commit_group;" ::: "memory");
}
__device__ __forceinline__ void cp_wait0() {
    asm volatile("cp.async.wait_group 0;" ::: "memory");
}
__device__ __forceinline__ void ldsm4(uint32_t* r, uint32_t addr) {
    asm volatile("ldmatrix.sync.aligned.m8n8.x4.shared.b16 {%0,%1,%2,%3}, [%4];"
                 : "=r"(r[0]), "=r"(r[1]), "=r"(r[2]), "=r"(r[3]) : "r"(addr));
}
__device__ __forceinline__ void mma16816(float* d, const uint32_t* a, const uint32_t* b) {
    asm volatile("mma.sync.aligned.m16n8k16.row.col.f32.f16.f16.f32 "
                 "{%0,%1,%2,%3}, {%4,%5,%6,%7}, {%8,%9}, {%0,%1,%2,%3};"
                 : "+f"(d[0]), "+f"(d[1]), "+f"(d[2]), "+f"(d[3])
                 : "r"(a[0]), "r"(a[1]), "r"(a[2]), "r"(a[3]), "r"(b[0]), "r"(b[1]));
}
__device__ __forceinline__ float softplusf(float x) {
    return fmaxf(x, 0.0f) + log1pf(expf(-fabsf(x)));
}

// ---------------------------------------------------------------------------
// fp32 -> (hi, lo) fp16 split converter: ONE launch for all 6 tensors.
// ---------------------------------------------------------------------------
__device__ __forceinline__ void cvt_body(const float* __restrict__ s,
                                         __half* __restrict__ hi, __half* __restrict__ lo,
                                         long n4, long i, long stride)
{
    for (; i < n4; i += stride) {
        float4 v = ((const float4*)s)[i];
        __half h0 = __float2half_rn(v.x), h1 = __float2half_rn(v.y);
        __half h2 = __float2half_rn(v.z), h3 = __float2half_rn(v.w);
        __half l0 = __float2half_rn(v.x - __half2float(h0));
        __half l1 = __float2half_rn(v.y - __half2float(h1));
        __half l2 = __float2half_rn(v.z - __half2float(h2));
        __half l3 = __float2half_rn(v.w - __half2float(h3));
        ((__half2*)hi)[2 * i]     = __halves2half2(h0, h1);
        ((__half2*)hi)[2 * i + 1] = __halves2half2(h2, h3);
        ((__half2*)lo)[2 * i]     = __halves2half2(l0, l1);
        ((__half2*)lo)[2 * i + 1] = __halves2half2(l2, l3);
    }
}

__global__ void cvt_all(const float* s0, __half* h0, __half* l0, long n0,
                        const float* s1, __half* h1, __half* l1, long n1,
                        const float* s2, __half* h2, __half* l2, long n2,
                        const float* s3, __half* h3, __half* l3, long n3,
                        const float* s4, __half* h4, __half* l4, long n4_,
                        const float* s5, __half* h5, __half* l5, long n5)
{
    const long i = blockIdx.x * (long)blockDim.x + threadIdx.x;
    const long st = (long)gridDim.x * blockDim.x;
    switch (blockIdx.y) {
        case 0: cvt_body(s0, h0, l0, n0, i, st); break;   // x (largest)
        case 1: cvt_body(s1, h1, l1, n1, i, st); break;
        case 2: cvt_body(s2, h2, l2, n2, i, st); break;
        case 3: cvt_body(s3, h3, l3, n3, i, st); break;
        case 4: cvt_body(s4, h4, l4, n4_, i, st); break;
        case 5: cvt_body(s5, h5, l5, n5, i, st); break;
    }
}

// ---------------------------------------------------------------------------
// fp16x2-split tensor-core GEMM: C[m,n] = sum_k A[m,k]*W[n,k] + bias[n]
// CTA tile 128(M)x128(N), 128 threads = 4 warps (2M x 2N), WARP TILE 64x64:
// 4x the MACs per smem byte of the 32x64 tile -> smem reads per tensor-cycle
// halve, lifting the ~66% smem-bandwidth tensor cap.
// K-chunk 32, 2-stage cp.async pipeline, ONE __syncthreads per chunk.
// Per B-fragment group: 24 MMAs issued term-major (acc reuse distance 8).
// 2 CTAs/SM (8 warps), 256-reg budget (acc 128 + frags ~40: no spills).
// 80B-padded rows -> ldmatrix conflict-free.
// EPI: 0 linear (hi/lo out), 1 relu (hi/lo out), 2 final head (fp32 out,
//      n-tile 0 = mu, 1 = var(softplus), mask -> NaN)
// ---------------------------------------------------------------------------
#define ROWB  80
#define TA_H  0
#define TA_L  10240
#define TB_H  20480
#define TB_L  30720
#define STG   40960
#define SBIAS (2*STG)
#define SMEMT (2*STG + 512)   // 82432 B -> 2 CTAs/SM

template<int EPI>
__global__ void __launch_bounds__(128, 2)
hgemm(const __half* __restrict__ Ah, const __half* __restrict__ Al, long lda, long Az,
      const __half* __restrict__ Wh, const __half* __restrict__ Wl, long Wz,
      const float* __restrict__ Bv, long Bz,
      __half* __restrict__ Ch, __half* __restrict__ Cl, long ldc, long Cz,
      float* __restrict__ Fout, const unsigned char* __restrict__ mask,
      int K)
{
    extern __shared__ char smem[];
    const uint32_t sb = smem_u32(smem);
    const int tid = threadIdx.x;
    const int wid = tid >> 5;
    const int l   = tid & 31;
    const long m0 = (long)blockIdx.x * 128;
    const long n0 = (long)blockIdx.y * 128;
    const int  z  = blockIdx.z;

    Ah += (long)z * Az + m0 * lda;
    Al += (long)z * Az + m0 * lda;
    Wh += (long)z * Wz + n0 * (long)K;
    Wl += (long)z * Wz + n0 * (long)K;
    Bv += (long)z * Bz + n0;

    ((float*)(smem + SBIAS))[tid] = Bv[tid];   // 128 threads, 128 floats

    // Load slots (K-chunk 32 = 64B data/row = 4 x 16B):
    //   each array: 128 rows x 4 chunks = 512 slots -> 4/thread per array
    const int r0 = tid >> 2,          c0 = tid & 3;
    const int r1 = (tid + 128) >> 2,  c1 = (tid + 128) & 3;
    const int r2 = (tid + 256) >> 2,  c2 = (tid + 256) & 3;
    const int r3 = (tid + 384) >> 2,  c3 = (tid + 384) & 3;

    const int NC = K >> 5;

    auto issue = [&](int stage) {
        const int k0 = stage << 5;
        const uint32_t st = sb + (uint32_t)(stage & 1) * STG;
        cp16(st + TA_H + r0 * ROWB + c0 * 16, Ah + (long)r0 * lda + k0 + c0 * 8);
        cp16(st + TA_H + r1 * ROWB + c1 * 16, Ah + (long)r1 * lda + k0 + c1 * 8);
        cp16(st + TA_H + r2 * ROWB + c2 * 16, Ah + (long)r2 * lda + k0 + c2 * 8);
        cp16(st + TA_H + r3 * ROWB + c3 * 16, Ah + (long)r3 * lda + k0 + c3 * 8);
        cp16(st + TA_L + r0 * ROWB + c0 * 16, Al + (long)r0 * lda + k0 + c0 * 8);
        cp16(st + TA_L + r1 * ROWB + c1 * 16, Al + (long)r1 * lda + k0 + c1 * 8);
        cp16(st + TA_L + r2 * ROWB + c2 * 16, Al + (long)r2 * lda + k0 + c2 * 8);
        cp16(st + TA_L + r3 * ROWB + c3 * 16, Al + (long)r3 * lda + k0 + c3 * 8);
        cp16(st + TB_H + r0 * ROWB + c0 * 16, Wh + (long)r0 * K + k0 + c0 * 8);
        cp16(st + TB_H + r1 * ROWB + c1 * 16, Wh + (long)r1 * K + k0 + c1 * 8);
        cp16(st + TB_H + r2 * ROWB + c2 * 16, Wh + (long)r2 * K + k0 + c2 * 8);
        cp16(st + TB_H + r3 * ROWB + c3 * 16, Wh + (long)r3 * K + k0 + c3 * 8);
        cp16(st + TB_L + r0 * ROWB + c0 * 16, Wl + (long)r0 * K + k0 + c0 * 8);
        cp16(st + TB_L + r1 * ROWB + c1 * 16, Wl + (long)r1 * K + k0 + c1 * 8);
        cp16(st + TB_L + r2 * ROWB + c2 * 16, Wl + (long)r2 * K + k0 + c2 * 8);
        cp16(st + TB_L + r3 * ROWB + c3 * 16, Wl + (long)r3 * K + k0 + c3 * 8);
    };

    issue(0); cp_commit();

    const int warp_m = wid & 1;        // 0..1 -> m offset *64
    const int warp_n = wid >> 1;       // 0..1 -> n offset *64
    const int a_r = l & 15;
    const int a_k = (l >> 4) * 8;
    const int b_r = (l & 7) + ((l >> 4) << 3);
    const int b_k = ((l >> 3) & 1) * 8;

    float acc[4][8][4] = {};

    for (int i = 0; i < NC; i++) {
        cp_wait0();            // stage i arrived (only group in flight)
        __syncthreads();       // + all warps finished stage i-1's buffer
        if (i + 1 < NC) { issue(i + 1); cp_commit(); }

        const uint32_t st = sb + (uint32_t)(i & 1) * STG;
        #pragma unroll
        for (int ks = 0; ks < 32; ks += 16) {
            // ---- A fragments: 4 m-tiles x hi/lo (32 regs), reused over 4 g ----
            uint32_t ahf[4][4], alf[4][4];
            #pragma unroll
            for (int mt = 0; mt < 4; mt++) {
                const uint32_t arow = (warp_m * 64 + mt * 16 + a_r) * ROWB + (ks + a_k) * 2;
                ldsm4(ahf[mt], st + TA_H + arow);
                ldsm4(alf[mt], st + TA_L + arow);
            }
            // ---- per n-group: load B frags, 24 MMAs term-major ----
            #pragma unroll
            for (int g = 0; g < 4; g++) {
                uint32_t bhf[4], blf[4];
                const uint32_t brow = (warp_n * 64 + g * 16 + b_r) * ROWB + (ks + b_k) * 2;
                ldsm4(bhf, st + TB_H + brow);
                ldsm4(blf, st + TB_L + brow);
                #pragma unroll
                for (int mt = 0; mt < 4; mt++)     // hi*hi: 8 independent
                    #pragma unroll
                    for (int pr = 0; pr < 2; pr++)
                        mma16816(acc[mt][g * 2 + pr], ahf[mt], &bhf[pr * 2]);
                #pragma unroll
                for (int mt = 0; mt < 4; mt++)     // hi*lo
                    #pragma unroll
                    for (int pr = 0; pr < 2; pr++)
                        mma16816(acc[mt][g * 2 + pr], ahf[mt], &blf[pr * 2]);
                #pragma unroll
                for (int mt = 0; mt < 4; mt++)     // lo*hi
                    #pragma unroll
                    for (int pr = 0; pr < 2; pr++)
                        mma16816(acc[mt][g * 2 + pr], alf[mt], &bhf[pr * 2]);
            }
        }
    }

    // ---- epilogue ----
    const float* bias_s = (const float*)(smem + SBIAS);

    #pragma unroll
    for (int mt = 0; mt < 4; mt++) {
        const long gr0 = m0 + warp_m * 64 + mt * 16 + (l >> 2);
        const long gr1 = gr0 + 8;
        #pragma unroll
        for (int nf = 0; nf < 8; nf++) {
            const int c = warp_n * 64 + nf * 8 + (l & 3) * 2;
            const float b0 = bias_s[c], b1 = bias_s[c + 1];
            float v00 = acc[mt][nf][0] + b0, v01 = acc[mt][nf][1] + b1;
            float v10 = acc[mt][nf][2] + b0, v11 = acc[mt][nf][3] + b1;

            if (EPI == 1) {
                v00 = fmaxf(v00, 0.f); v01 = fmaxf(v01, 0.f);
                v10 = fmaxf(v10, 0.f); v11 = fmaxf(v11, 0.f);
            }

            if (EPI != 2) {
                __half h00 = __float2half_rn(v00), h01 = __float2half_rn(v01);
                __half h10 = __float2half_rn(v10), h11 = __float2half_rn(v11);
                __half l00 = __float2half_rn(v00 - __half2float(h00));
                __half l01 = __float2half_rn(v01 - __half2float(h01));
                __half l10 = __float2half_rn(v10 - __half2float(h10));
                __half l11 = __float2half_rn(v11 - __half2float(h11));
                __half* ch0 = Ch + (long)z * Cz + gr0 * ldc + n0 + c;
                __half* ch1 = Ch + (long)z * Cz + gr1 * ldc + n0 + c;
                __half* cl0 = Cl + (long)z * Cz + gr0 * ldc + n0 + c;
                __half* cl1 = Cl + (long)z * Cz + gr1 * ldc + n0 + c;
                *(__half2*)ch0 = __halves2half2(h00, h01);
                *(__half2*)ch1 = __halves2half2(h10, h11);
                *(__half2*)cl0 = __halves2half2(l00, l01);
                *(__half2*)cl1 = __halves2half2(l10, l11);
            } else {
                const int y = blockIdx.y;           // 0 = mu, 1 = var
                if (y == 1) {
                    v00 = 0.01f + 0.99f * softplusf(v00);
                    v01 = 0.01f + 0.99f * softplusf(v01);
                    v10 = 0.01f + 0.99f * softplusf(v10);
                    v11 = 0.01f + 0.99f * softplusf(v11);
                }
                const long f0 = gr0 * PD + z;
                const long f1 = gr1 * PD + z;
                const float nanv = __int_as_float(0x7FC00000);
                float2 o0v = make_float2(v00, v01);
                float2 o1v = make_float2(v10, v11);
                if (mask[f0] != 0) { o0v.x = nanv; o0v.y = nanv; }
                if (mask[f1] != 0) { o1v.x = nanv; o1v.y = nanv; }
                float* ob = Fout + (long)y * ((long)NP * OUTD);
                *(float2*)(ob + f0 * OUTD + c) = o0v;
                *(float2*)(ob + f1 * OUTD + c) = o1v;
            }
        }
    }
}

extern "C" void kernel_launch(void* const* d_in, const int* in_sizes, int n_in,
                              void* d_out, int out_size)
{
    const float* x    = (const float*)d_in[0];
    const unsigned char* mask = (const unsigned char*)d_in[1];
    const float* W_in = (const float*)d_in[2];
    const float* b_in = (const float*)d_in[3];
    const float* W1   = (const float*)d_in[4];
    const float* b1   = (const float*)d_in[5];
    const float* W2   = (const float*)d_in[6];
    const float* b2   = (const float*)d_in[7];
    const float* W3   = (const float*)d_in[8];
    const float* b3   = (const float*)d_in[9];
    const float* Wout = (const float*)d_in[10];
    const float* bout = (const float*)d_in[11];
    float* out = (float*)d_out;

    __half *xh, *xl, *h0h, *h0l, *h1h, *h1l, *h2h, *h2l, *h3h, *h3l;
    __half *wih, *wil, *w1h, *w1l, *w2h, *w2l, *w3h, *w3l, *woh, *wol;
    cudaGetSymbolAddress((void**)&xh,  g_xh);  cudaGetSymbolAddress((void**)&xl,  g_xl);
    cudaGetSymbolAddress((void**)&h0h, g_h0h); cudaGetSymbolAddress((void**)&h0l, g_h0l);
    cudaGetSymbolAddress((void**)&h1h, g_h1h); cudaGetSymbolAddress((void**)&h1l, g_h1l);
    cudaGetSymbolAddress((void**)&h2h, g_h2h); cudaGetSymbolAddress((void**)&h2l, g_h2l);
    cudaGetSymbolAddress((void**)&h3h, g_h3h); cudaGetSymbolAddress((void**)&h3l, g_h3l);
    cudaGetSymbolAddress((void**)&wih, g_wih); cudaGetSymbolAddress((void**)&wil, g_wil);
    cudaGetSymbolAddress((void**)&w1h, g_w1h); cudaGetSymbolAddress((void**)&w1l, g_w1l);
    cudaGetSymbolAddress((void**)&w2h, g_w2h); cudaGetSymbolAddress((void**)&w2l, g_w2l);
    cudaGetSymbolAddress((void**)&w3h, g_w3h); cudaGetSymbolAddress((void**)&w3l, g_w3l);
    cudaGetSymbolAddress((void**)&woh, g_woh); cudaGetSymbolAddress((void**)&wol, g_wol);

    cudaFuncSetAttribute(hgemm<0>, cudaFuncAttributeMaxDynamicSharedMemorySize, SMEMT);
    cudaFuncSetAttribute(hgemm<1>, cudaFuncAttributeMaxDynamicSharedMemorySize, SMEMT);
    cudaFuncSetAttribute(hgemm<2>, cudaFuncAttributeMaxDynamicSharedMemorySize, SMEMT);

    // ---- all conversions: ONE launch ----
    cvt_all<<<dim3(512, 6), 256>>>(
        x,    xh,  xl,  (long)NP * IND / 4,
        W_in, wih, wil, (long)PD * HH0 * IND / 4,
        W1,   w1h, w1l, (long)HH1 * HH0 / 4,
        W2,   w2h, w2l, (long)HH2 * HH1 / 4,
        W3,   w3h, w3l, (long)HH3 * HH2 / 4,
        Wout, woh, wol, (long)PD * 2 * OUTD * HH3 / 4);

    // ---- Layer 0: per-p input projection (linear) ----
    hgemm<0><<<dim3(NPTS / 128, HH0 / 128, PD), 128, SMEMT>>>(
        xh, xl, (long)PD * IND, (long)IND,
        wih, wil, (long)HH0 * IND,
        b_in, (long)HH0,
        h0h, h0l, (long)PD * HH0, (long)HH0,
        nullptr, nullptr, IND);

    // ---- Layer 1: relu ----
    hgemm<1><<<dim3(NP / 128, HH1 / 128, 1), 128, SMEMT>>>(
        h0h, h0l, HH0, 0, w1h, w1l, 0, b1, 0,
        h1h, h1l, HH1, 0, nullptr, nullptr, HH0);

    // ---- Layer 2: relu ----
    hgemm<1><<<dim3(NP / 128, HH2 / 128, 1), 128, SMEMT>>>(
        h1h, h1l, HH1, 0, w2h, w2l, 0, b2, 0,
        h2h, h2l, HH2, 0, nullptr, nullptr, HH1);

    // ---- Layer 3: relu ----
    hgemm<1><<<dim3(NP / 128, HH3 / 128, 1), 128, SMEMT>>>(
        h2h, h2l, HH2, 0, w3h, w3l, 0, b3, 0,
        h3h, h3l, HH3, 0, nullptr, nullptr, HH2);

    // ---- Output head: y = 0 mu, y = 1 var(softplus), mask -> NaN ----
    hgemm<2><<<dim3(NPTS / 128, 2, PD), 128, SMEMT>>>(
        h3h, h3l, (long)PD * HH3, (long)HH3,
        woh, wol, (long)(2 * OUTD) * HH3,
        bout, (long)(2 * OUTD),
        nullptr, nullptr, 0, 0,
        out, mask, HH3);
}